// round 7
// baseline (speedup 1.0000x reference)
#include <cuda_runtime.h>
#include <math.h>

#define NTASK   2000
#define NSUP    25
#define NQ      75
#define DIM     640
#define KW      5
#define NLAYERS 20
#define R       80
#define DC      64
#define NCHUNK  (DIM / DC)
#define PADC    66           // 5*66=330 == 10 mod 32 -> 16 distinct banks for tj=0..15
#define PADG    81
#define PADU    8
#define EPS     1e-6f
#define NTHR    256

__global__ __launch_bounds__(NTHR, 2)
void fewshot_kernel(const float* __restrict__ Zs_g,
                    const int*   __restrict__ Y_g,
                    const float* __restrict__ Zq_g,
                    const float* __restrict__ t1_p,
                    const float* __restrict__ gm_p,
                    const float* __restrict__ t2_p,
                    float*       __restrict__ out)
{
    __shared__ __align__(16) float Zx[R * PADC];   // 21120 B ; later U_s/GU_s
    __shared__ __align__(16) float G [R * PADG];   // 25920 B ; support staging early
    __shared__ float invden_s[KW], halfnn_s[KW], gV_s[KW], ssq_s[KW], cnt_s[KW];
    __shared__ int   Y_sh[NSUP];

    float* Sup  = G;
    float* U_s  = Zx;
    float* GU_s = Zx + NQ * PADU;

    const int b = blockIdx.x;
    const int t = threadIdx.x;

    const float c      = log1pf(expf(t1_p[0]));
    const float g      = log1pf(expf(gm_p[0]));
    const float inv_t2 = 1.0f / (log1pf(expf(t2_p[0])) + 1.0f);

    if (t < NSUP) Y_sh[t] = Y_g[b * NSUP + t];
    __syncthreads();

    // ---- Phase 1: Gram of Zx = [c*Zq ; c*class_sums], 80x80x640 ----
    // 16x16 grid of 5x5 tiles, one per thread. Within a warp: 2 ti values
    // (broadcast av), 16 tj values hitting 16 distinct bank-pairs (1 wf bv).
    const int ti = t >> 4, tj = t & 15;
    const int ri = ti * 5, rj = tj * 5;

    unsigned long long acc[25];
    #pragma unroll
    for (int i = 0; i < 25; i++) acc[i] = 0ull;

    const float* Zq_b = Zq_g + (size_t)b * NQ   * DIM;
    const float* Zs_b = Zs_g + (size_t)b * NSUP * DIM;

    for (int ch = 0; ch < NCHUNK; ch++) {
        const int d0 = ch * DC;
        // stage query rows (scaled); float2 stores (rows 8B-aligned)
        for (int idx = t; idx < NQ * (DC / 4); idx += NTHR) {
            const int q = idx / (DC / 4);
            const int v = idx % (DC / 4);
            float4 x = *(const float4*)(Zq_b + q * DIM + d0 + 4 * v);
            float2* dst = (float2*)&Zx[q * PADC + 4 * v];
            dst[0] = make_float2(c * x.x, c * x.y);
            dst[1] = make_float2(c * x.z, c * x.w);
        }
        // stage raw support rows
        for (int idx = t; idx < NSUP * (DC / 4); idx += NTHR) {
            const int s = idx / (DC / 4);
            const int v = idx % (DC / 4);
            float4 x = *(const float4*)(Zs_b + s * DIM + d0 + 4 * v);
            float2* dst = (float2*)&Sup[s * PADC + 4 * v];
            dst[0] = make_float2(x.x, x.y);
            dst[1] = make_float2(x.z, x.w);
        }
        __syncthreads();
        // class sums -> rows 75..79 (scaled)
        for (int idx = t; idx < KW * DC; idx += NTHR) {
            const int dl = idx & (DC - 1);
            const int k  = idx >> 6;
            float s = 0.f;
            #pragma unroll
            for (int j = 0; j < NSUP; j++)
                if (Y_sh[j] == k) s += Sup[j * PADC + dl];
            Zx[(NQ + k) * PADC + dl] = c * s;
        }
        __syncthreads();

        #pragma unroll 4
        for (int dl = 0; dl < DC; dl += 2) {
            unsigned long long av[5], bv[5];
            #pragma unroll
            for (int i = 0; i < 5; i++)
                av[i] = *(const unsigned long long*)&Zx[(ri + i) * PADC + dl];
            #pragma unroll
            for (int j = 0; j < 5; j++)
                bv[j] = *(const unsigned long long*)&Zx[(rj + j) * PADC + dl];
            #pragma unroll
            for (int i = 0; i < 5; i++)
                #pragma unroll
                for (int j = 0; j < 5; j++)
                    asm("fma.rn.f32x2 %0, %1, %2, %0;"
                        : "+l"(acc[i * 5 + j]) : "l"(av[i]), "l"(bv[j]));
        }
        __syncthreads();
    }

    // finalize: fold packed halves into G
    #pragma unroll
    for (int i = 0; i < 5; i++)
        #pragma unroll
        for (int j = 0; j < 5; j++) {
            const unsigned long long x = acc[i * 5 + j];
            const float lo = __uint_as_float((unsigned)(x & 0xffffffffu));
            const float hi = __uint_as_float((unsigned)(x >> 32));
            G[(ri + i) * PADG + (rj + j)] = lo + hi;
        }
    __syncthreads();

    // ---- init per-class state ----
    if (t < KW) {
        const int k = t;
        float cn = 0.f;
        #pragma unroll
        for (int j = 0; j < NSUP; j++) cn += (Y_sh[j] == k) ? 1.f : 0.f;
        const float ssq = G[(NQ + k) * PADG + (NQ + k)];
        const float iv  = 1.0f / cn;
        cnt_s[k]    = cn;
        ssq_s[k]    = ssq;
        invden_s[k] = iv;
        halfnn_s[k] = 0.5f * ssq * iv * iv;
        gV_s[k]     = g;
    }
    __syncthreads();

    const int q = t;
    float sk[KW], gu[KW];
    #pragma unroll
    for (int k = 0; k < KW; k++) gu[k] = 0.f;
    if (q < NQ) {
        #pragma unroll
        for (int k = 0; k < KW; k++) sk[k] = G[(NQ + k) * PADG + q];
    }

    // ---- Phase 2: 20 layers in SMEM ----
    for (int it = 0; it < NLAYERS; it++) {
        float u[KW];
        if (q < NQ) {
            float a[KW], m = -1e30f;
            #pragma unroll
            for (int k = 0; k < KW; k++) {
                a[k] = inv_t2 * ((gu[k] + sk[k]) * invden_s[k] - halfnn_s[k] + gV_s[k]);
                m = fmaxf(m, a[k]);
            }
            float ssum = 0.f;
            #pragma unroll
            for (int k = 0; k < KW; k++) { u[k] = __expf(a[k] - m); ssum += u[k]; }
            const float r = 1.0f / ssum;
            #pragma unroll
            for (int k = 0; k < KW; k++) u[k] *= r;

            if (it == NLAYERS - 1) {
                float* o = out + ((size_t)b * NQ + q) * KW;
                #pragma unroll
                for (int k = 0; k < KW; k++) o[k] = u[k];
            } else {
                #pragma unroll
                for (int k = 0; k < KW; k++) U_s[q * PADU + k] = u[k];
            }
        }
        if (it == NLAYERS - 1) break;
        __syncthreads();

        // GU = G[0:75,0:75] @ U  -- unrolled x5, loads batched per group
        if (q < NQ) {
            float ng0 = 0.f, ng1 = 0.f, ng2 = 0.f, ng3 = 0.f, ng4 = 0.f;
            const float* Grow = &G[q * PADG];
            #pragma unroll 3
            for (int qp = 0; qp < NQ; qp += 5) {
                float  gv[5];
                float4 u4[5];
                float  u5[5];
                #pragma unroll
                for (int j = 0; j < 5; j++) {
                    gv[j] = Grow[qp + j];
                    u4[j] = *(const float4*)&U_s[(qp + j) * PADU];
                    u5[j] = U_s[(qp + j) * PADU + 4];
                }
                #pragma unroll
                for (int j = 0; j < 5; j++) {
                    ng0 += gv[j] * u4[j].x; ng1 += gv[j] * u4[j].y;
                    ng2 += gv[j] * u4[j].z; ng3 += gv[j] * u4[j].w;
                    ng4 += gv[j] * u5[j];
                }
            }
            gu[0] = ng0; gu[1] = ng1; gu[2] = ng2; gu[3] = ng3; gu[4] = ng4;
            GU_s[q * PADU + 0] = ng0; GU_s[q * PADU + 1] = ng1;
            GU_s[q * PADU + 2] = ng2; GU_s[q * PADU + 3] = ng3;
            GU_s[q * PADU + 4] = ng4;
        }
        __syncthreads();

        // per-class reductions: warp k handles class k (8 warps available)
        const int w = t >> 5, lane = t & 31;
        if (w < KW) {
            const int k = w;
            float usum = 0.f, ups = 0.f, ugu = 0.f;
            for (int qq = lane; qq < NQ; qq += 32) {
                const float uv = U_s[qq * PADU + k];
                usum += uv;
                ups  += uv * G[(NQ + k) * PADG + qq];
                ugu  += uv * GU_s[qq * PADU + k];
            }
            #pragma unroll
            for (int o = 16; o > 0; o >>= 1) {
                usum += __shfl_down_sync(0xffffffffu, usum, o);
                ups  += __shfl_down_sync(0xffffffffu, ups,  o);
                ugu  += __shfl_down_sync(0xffffffffu, ugu,  o);
            }
            if (lane == 0) {
                const float den = usum + cnt_s[k];
                const float iv  = 1.0f / den;
                const float nn  = ugu + 2.f * ups + ssq_s[k];
                invden_s[k] = iv;
                halfnn_s[k] = 0.5f * nn * iv * iv;
                gV_s[k]     = g * (logf(usum / (float)NQ + EPS) + 1.0f);
            }
        }
        __syncthreads();
    }
}

extern "C" void kernel_launch(void* const* d_in, const int* in_sizes, int n_in,
                              void* d_out, int out_size)
{
    const float* Zs = (const float*)d_in[0];
    const int*   Y  = (const int*)  d_in[1];
    const float* Zq = (const float*)d_in[2];
    const float* t1 = (const float*)d_in[3];
    const float* gm = (const float*)d_in[4];
    const float* t2 = (const float*)d_in[5];
    fewshot_kernel<<<NTASK, NTHR>>>(Zs, Y, Zq, t1, gm, t2, (float*)d_out);
}

// round 9
// speedup vs baseline: 1.0432x; 1.0432x over previous
#include <cuda_runtime.h>
#include <math.h>

#define NTASK   2000
#define NSUP    25
#define NQ      75
#define DIM     640
#define KW      5
#define NLAYERS 20
#define R       80
#define DC      64
#define NCHUNK  (DIM / DC)
#define PADC    66
#define PADG    81
#define PADU    8
#define EPS     1e-6f
#define NTHR    256
#define NTILES  136          // upper-triangle 5x5 tiles of the 16x16 grid

__global__ __launch_bounds__(NTHR, 2)
void fewshot_kernel(const float* __restrict__ Zs_g,
                    const int*   __restrict__ Y_g,
                    const float* __restrict__ Zq_g,
                    const float* __restrict__ t1_p,
                    const float* __restrict__ gm_p,
                    const float* __restrict__ t2_p,
                    float*       __restrict__ out)
{
    __shared__ __align__(16) float Zx[R * PADC];   // later U_s/GU_s
    __shared__ __align__(16) float G [R * PADG];   // support staging early
    __shared__ float invden_s[KW], halfnn_s[KW], gV_s[KW], ssq_s[KW], cnt_s[KW];
    __shared__ int   Y_sh[NSUP];

    float* Sup  = G;
    float* U_s  = Zx;
    float* GU_s = Zx + NQ * PADU;

    const int b = blockIdx.x;
    const int t = threadIdx.x;

    const float c      = log1pf(expf(t1_p[0]));
    const float g      = log1pf(expf(gm_p[0]));
    const float inv_t2 = 1.0f / (log1pf(expf(t2_p[0])) + 1.0f);

    if (t < NSUP) Y_sh[t] = Y_g[b * NSUP + t];
    __syncthreads();

    // ---- Phase 1: symmetric Gram, upper-triangle tiles only ----
    const bool act = (t < NTILES);
    int ti = 0, tj = 0;
    {
        int rem = t < NTILES ? t : 0;
        #pragma unroll
        for (int r = 0; r < 16; r++) {
            if (rem >= 16 - ti) { rem -= 16 - ti; ti++; }
        }
        tj = ti + rem;
    }
    const int ri = ti * 5, rj = tj * 5;

    unsigned long long acc[25];
    #pragma unroll
    for (int i = 0; i < 25; i++) acc[i] = 0ull;

    const float* Zq_b = Zq_g + (size_t)b * NQ   * DIM;
    const float* Zs_b = Zs_g + (size_t)b * NSUP * DIM;

    for (int ch = 0; ch < NCHUNK; ch++) {
        const int d0 = ch * DC;
        // stage query rows (scaled) -- all 256 threads
        for (int idx = t; idx < NQ * (DC / 4); idx += NTHR) {
            const int q = idx / (DC / 4);
            const int v = idx % (DC / 4);
            float4 x = *(const float4*)(Zq_b + q * DIM + d0 + 4 * v);
            float2* dst = (float2*)&Zx[q * PADC + 4 * v];
            dst[0] = make_float2(c * x.x, c * x.y);
            dst[1] = make_float2(c * x.z, c * x.w);
        }
        // stage raw support rows
        for (int idx = t; idx < NSUP * (DC / 4); idx += NTHR) {
            const int s = idx / (DC / 4);
            const int v = idx % (DC / 4);
            float4 x = *(const float4*)(Zs_b + s * DIM + d0 + 4 * v);
            float2* dst = (float2*)&Sup[s * PADC + 4 * v];
            dst[0] = make_float2(x.x, x.y);
            dst[1] = make_float2(x.z, x.w);
        }
        __syncthreads();
        // class sums -> rows 75..79 (scaled)
        for (int idx = t; idx < KW * DC; idx += NTHR) {
            const int dl = idx & (DC - 1);
            const int k  = idx >> 6;
            float s = 0.f;
            #pragma unroll
            for (int j = 0; j < NSUP; j++)
                if (Y_sh[j] == k) s += Sup[j * PADC + dl];
            Zx[(NQ + k) * PADC + dl] = c * s;
        }
        __syncthreads();

        if (act) {
            #pragma unroll 4
            for (int dl = 0; dl < DC; dl += 2) {
                unsigned long long av[5], bv[5];
                #pragma unroll
                for (int i = 0; i < 5; i++)
                    av[i] = *(const unsigned long long*)&Zx[(ri + i) * PADC + dl];
                #pragma unroll
                for (int j = 0; j < 5; j++)
                    bv[j] = *(const unsigned long long*)&Zx[(rj + j) * PADC + dl];
                #pragma unroll
                for (int i = 0; i < 5; i++)
                    #pragma unroll
                    for (int j = 0; j < 5; j++)
                        asm("fma.rn.f32x2 %0, %1, %2, %0;"
                            : "+l"(acc[i * 5 + j]) : "l"(av[i]), "l"(bv[j]));
            }
        }
        __syncthreads();
    }

    // finalize: fold packed halves, write tile + mirror
    if (act) {
        #pragma unroll
        for (int i = 0; i < 5; i++)
            #pragma unroll
            for (int j = 0; j < 5; j++) {
                const unsigned long long x = acc[i * 5 + j];
                const float lo = __uint_as_float((unsigned)(x & 0xffffffffu));
                const float hi = __uint_as_float((unsigned)(x >> 32));
                const float v  = lo + hi;
                G[(ri + i) * PADG + (rj + j)] = v;
                G[(rj + j) * PADG + (ri + i)] = v;
            }
    }
    __syncthreads();

    // ---- init per-class state ----
    if (t < KW) {
        const int k = t;
        float cn = 0.f;
        #pragma unroll
        for (int j = 0; j < NSUP; j++) cn += (Y_sh[j] == k) ? 1.f : 0.f;
        const float ssq = G[(NQ + k) * PADG + (NQ + k)];
        const float iv  = 1.0f / cn;
        cnt_s[k]    = cn;
        ssq_s[k]    = ssq;
        invden_s[k] = iv;
        halfnn_s[k] = 0.5f * ssq * iv * iv;
        gV_s[k]     = g;
    }
    __syncthreads();

    const int q = t;
    float sk[KW], gu[KW];
    #pragma unroll
    for (int k = 0; k < KW; k++) gu[k] = 0.f;
    if (q < NQ) {
        #pragma unroll
        for (int k = 0; k < KW; k++) sk[k] = G[(NQ + k) * PADG + q];
    }

    // ---- Phase 2: 20 layers in SMEM ----
    for (int it = 0; it < NLAYERS; it++) {
        float u[KW];
        if (q < NQ) {
            float a[KW], m = -1e30f;
            #pragma unroll
            for (int k = 0; k < KW; k++) {
                a[k] = inv_t2 * ((gu[k] + sk[k]) * invden_s[k] - halfnn_s[k] + gV_s[k]);
                m = fmaxf(m, a[k]);
            }
            float ssum = 0.f;
            #pragma unroll
            for (int k = 0; k < KW; k++) { u[k] = __expf(a[k] - m); ssum += u[k]; }
            const float r = 1.0f / ssum;
            #pragma unroll
            for (int k = 0; k < KW; k++) u[k] *= r;

            if (it == NLAYERS - 1) {
                float* o = out + ((size_t)b * NQ + q) * KW;
                #pragma unroll
                for (int k = 0; k < KW; k++) o[k] = u[k];
            } else {
                #pragma unroll
                for (int k = 0; k < KW; k++) U_s[q * PADU + k] = u[k];
            }
        }
        if (it == NLAYERS - 1) break;
        __syncthreads();

        // GU = G[0:75,0:75] @ U  -- unrolled x5, batched loads
        if (q < NQ) {
            float ng0 = 0.f, ng1 = 0.f, ng2 = 0.f, ng3 = 0.f, ng4 = 0.f;
            const float* Grow = &G[q * PADG];
            #pragma unroll 3
            for (int qp = 0; qp < NQ; qp += 5) {
                float  gv[5];
                float4 u4[5];
                float  u5[5];
                #pragma unroll
                for (int j = 0; j < 5; j++) {
                    gv[j] = Grow[qp + j];
                    u4[j] = *(const float4*)&U_s[(qp + j) * PADU];
                    u5[j] = U_s[(qp + j) * PADU + 4];
                }
                #pragma unroll
                for (int j = 0; j < 5; j++) {
                    ng0 += gv[j] * u4[j].x; ng1 += gv[j] * u4[j].y;
                    ng2 += gv[j] * u4[j].z; ng3 += gv[j] * u4[j].w;
                    ng4 += gv[j] * u5[j];
                }
            }
            gu[0] = ng0; gu[1] = ng1; gu[2] = ng2; gu[3] = ng3; gu[4] = ng4;
            GU_s[q * PADU + 0] = ng0; GU_s[q * PADU + 1] = ng1;
            GU_s[q * PADU + 2] = ng2; GU_s[q * PADU + 3] = ng3;
            GU_s[q * PADU + 4] = ng4;
        }
        __syncthreads();

        // per-class reductions: warp k handles class k
        const int w = t >> 5, lane = t & 31;
        if (w < KW) {
            const int k = w;
            float usum = 0.f, ups = 0.f, ugu = 0.f;
            for (int qq = lane; qq < NQ; qq += 32) {
                const float uv = U_s[qq * PADU + k];
                usum += uv;
                ups  += uv * G[(NQ + k) * PADG + qq];
                ugu  += uv * GU_s[qq * PADU + k];
            }
            #pragma unroll
            for (int o = 16; o > 0; o >>= 1) {
                usum += __shfl_down_sync(0xffffffffu, usum, o);
                ups  += __shfl_down_sync(0xffffffffu, ups,  o);
                ugu  += __shfl_down_sync(0xffffffffu, ugu,  o);
            }
            if (lane == 0) {
                const float den = usum + cnt_s[k];
                const float iv  = 1.0f / den;
                const float nn  = ugu + 2.f * ups + ssq_s[k];
                invden_s[k] = iv;
                halfnn_s[k] = 0.5f * nn * iv * iv;
                gV_s[k]     = g * (logf(usum / (float)NQ + EPS) + 1.0f);
            }
        }
        __syncthreads();
    }
}

extern "C" void kernel_launch(void* const* d_in, const int* in_sizes, int n_in,
                              void* d_out, int out_size)
{
    const float* Zs = (const float*)d_in[0];
    const int*   Y  = (const int*)  d_in[1];
    const float* Zq = (const float*)d_in[2];
    const float* t1 = (const float*)d_in[3];
    const float* gm = (const float*)d_in[4];
    const float* t2 = (const float*)d_in[5];
    fewshot_kernel<<<NTASK, NTHR>>>(Zs, Y, Zq, t1, gm, t2, (float*)d_out);
}

// round 13
// speedup vs baseline: 1.2645x; 1.2121x over previous
#include <cuda_runtime.h>
#include <math.h>
#include <stdint.h>

#define NTASK   2000
#define NSUP    25
#define NQ      75
#define DIM     640
#define KW      5
#define NLAYERS 20
#define R       80
#define DC      64
#define NCHUNK  (DIM / DC)
#define PADC    68           // 16B-aligned rows for cp.async
#define PADG    81
#define PADU    8
#define EPS     1e-6f
#define NTHR    256
#define NTILES  136

#define ZX_FLOATS  (R * PADC)       // 5440
#define SUP_FLOATS (NSUP * PADC)    // 1700
#define G_OFF      (2 * ZX_FLOATS + 2 * SUP_FLOATS)
#define SMEM_FLOATS (G_OFF + R * PADG)
#define SMEM_BYTES  (SMEM_FLOATS * 4)   // 83040

__device__ __forceinline__ void cpa16(uint32_t dst, const float* src) {
    asm volatile("cp.async.cg.shared.global [%0], [%1], 16;" :: "r"(dst), "l"(src));
}

__global__ __launch_bounds__(NTHR, 2)
void fewshot_kernel(const float* __restrict__ Zs_g,
                    const int*   __restrict__ Y_g,
                    const float* __restrict__ Zq_g,
                    const float* __restrict__ t1_p,
                    const float* __restrict__ gm_p,
                    const float* __restrict__ t2_p,
                    float*       __restrict__ out)
{
    extern __shared__ __align__(16) float smem[];
    float* ZxB[2]  = { smem, smem + ZX_FLOATS };
    float* SupB[2] = { smem + 2 * ZX_FLOATS, smem + 2 * ZX_FLOATS + SUP_FLOATS };
    float* G       = smem + G_OFF;
    float* U_s  = smem;                 // aliases ZxB[0] in phase 2
    float* GU_s = smem + NQ * PADU;

    __shared__ float invden_s[KW], halfnn_s[KW], gV_s[KW], ssq_s[KW], cnt_s[KW];
    __shared__ int   Y_sh[NSUP];

    const int b = blockIdx.x;
    const int t = threadIdx.x;

    const float c      = log1pf(expf(t1_p[0]));
    const float c2     = c * c;
    const float g      = log1pf(expf(gm_p[0]));
    const float inv_t2 = 1.0f / (log1pf(expf(t2_p[0])) + 1.0f);

    if (t < NSUP) Y_sh[t] = Y_g[b * NSUP + t];

    const uint32_t zx_u32[2]  = { (uint32_t)__cvta_generic_to_shared(ZxB[0]),
                                  (uint32_t)__cvta_generic_to_shared(ZxB[1]) };
    const uint32_t sup_u32[2] = { (uint32_t)__cvta_generic_to_shared(SupB[0]),
                                  (uint32_t)__cvta_generic_to_shared(SupB[1]) };

    const float* Zq_b = Zq_g + (size_t)b * NQ   * DIM;
    const float* Zs_b = Zs_g + (size_t)b * NSUP * DIM;

    // symmetric tile unrank (upper triangle of 16x16 grid of 5x5 tiles)
    const bool act = (t < NTILES);
    int ti = 0, tj = 0;
    {
        int rem = act ? t : 0;
        #pragma unroll
        for (int r = 0; r < 16; r++)
            if (rem >= 16 - ti) { rem -= 16 - ti; ti++; }
        tj = ti + rem;
    }
    const int ri = ti * 5, rj = tj * 5;

    unsigned long long acc[25];
    #pragma unroll
    for (int i = 0; i < 25; i++) acc[i] = 0ull;

    // ---- stage chunk 0 ----
    {
        const int d0 = 0;
        for (int idx = t; idx < NQ * 16; idx += NTHR) {
            const int row = idx >> 4, v = idx & 15;
            cpa16(zx_u32[0] + (row * PADC + 4 * v) * 4, Zq_b + row * DIM + d0 + 4 * v);
        }
        for (int idx = t; idx < NSUP * 16; idx += NTHR) {
            const int row = idx >> 4, v = idx & 15;
            cpa16(sup_u32[0] + (row * PADC + 4 * v) * 4, Zs_b + row * DIM + d0 + 4 * v);
        }
        asm volatile("cp.async.commit_group;");
    }

    for (int ch = 0; ch < NCHUNK; ch++) {
        const int cur = ch & 1, nxt = (ch + 1) & 1;
        // issue next chunk's loads into the other buffer
        if (ch + 1 < NCHUNK) {
            const int d0 = (ch + 1) * DC;
            for (int idx = t; idx < NQ * 16; idx += NTHR) {
                const int row = idx >> 4, v = idx & 15;
                cpa16(zx_u32[nxt] + (row * PADC + 4 * v) * 4, Zq_b + row * DIM + d0 + 4 * v);
            }
            for (int idx = t; idx < NSUP * 16; idx += NTHR) {
                const int row = idx >> 4, v = idx & 15;
                cpa16(sup_u32[nxt] + (row * PADC + 4 * v) * 4, Zs_b + row * DIM + d0 + 4 * v);
            }
        }
        asm volatile("cp.async.commit_group;");
        asm volatile("cp.async.wait_group 1;");   // chunk ch resident
        __syncthreads();

        // class sums (raw) -> rows 75..79 of current Zx buffer
        float* Zx  = ZxB[cur];
        float* Sup = SupB[cur];
        for (int idx = t; idx < KW * DC; idx += NTHR) {
            const int dl = idx & (DC - 1);
            const int k  = idx >> 6;
            float s = 0.f;
            #pragma unroll
            for (int j = 0; j < NSUP; j++)
                if (Y_sh[j] == k) s += Sup[j * PADC + dl];
            Zx[(NQ + k) * PADC + dl] = s;
        }
        __syncthreads();

        if (act) {
            #pragma unroll 4
            for (int dl = 0; dl < DC; dl += 2) {
                unsigned long long av[5], bv[5];
                #pragma unroll
                for (int i = 0; i < 5; i++)
                    av[i] = *(const unsigned long long*)&Zx[(ri + i) * PADC + dl];
                #pragma unroll
                for (int j = 0; j < 5; j++)
                    bv[j] = *(const unsigned long long*)&Zx[(rj + j) * PADC + dl];
                #pragma unroll
                for (int i = 0; i < 5; i++)
                    #pragma unroll
                    for (int j = 0; j < 5; j++)
                        asm("fma.rn.f32x2 %0, %1, %2, %0;"
                            : "+l"(acc[i * 5 + j]) : "l"(av[i]), "l"(bv[j]));
            }
        }
        __syncthreads();
    }

    // finalize: fold halves, scale by c^2, write tile + mirror
    if (act) {
        #pragma unroll
        for (int i = 0; i < 5; i++)
            #pragma unroll
            for (int j = 0; j < 5; j++) {
                const unsigned long long x = acc[i * 5 + j];
                const float lo = __uint_as_float((unsigned)(x & 0xffffffffu));
                const float hi = __uint_as_float((unsigned)(x >> 32));
                const float v  = (lo + hi) * c2;
                G[(ri + i) * PADG + (rj + j)] = v;
                G[(rj + j) * PADG + (ri + i)] = v;
            }
    }
    __syncthreads();

    // ---- init per-class state ----
    if (t < KW) {
        const int k = t;
        float cn = 0.f;
        #pragma unroll
        for (int j = 0; j < NSUP; j++) cn += (Y_sh[j] == k) ? 1.f : 0.f;
        const float ssq = G[(NQ + k) * PADG + (NQ + k)];
        const float iv  = 1.0f / cn;
        cnt_s[k]    = cn;
        ssq_s[k]    = ssq;
        invden_s[k] = iv;
        halfnn_s[k] = 0.5f * ssq * iv * iv;
        gV_s[k]     = g;
    }
    __syncthreads();

    const int q = t;
    float sk[KW], gu[KW];
    #pragma unroll
    for (int k = 0; k < KW; k++) gu[k] = 0.f;
    if (q < NQ) {
        #pragma unroll
        for (int k = 0; k < KW; k++) sk[k] = G[(NQ + k) * PADG + q];
    }

    // ---- Phase 2: 20 layers in SMEM ----
    for (int it = 0; it < NLAYERS; it++) {
        float u[KW];
        if (q < NQ) {
            float a[KW], m = -1e30f;
            #pragma unroll
            for (int k = 0; k < KW; k++) {
                a[k] = inv_t2 * ((gu[k] + sk[k]) * invden_s[k] - halfnn_s[k] + gV_s[k]);
                m = fmaxf(m, a[k]);
            }
            float ssum = 0.f;
            #pragma unroll
            for (int k = 0; k < KW; k++) { u[k] = __expf(a[k] - m); ssum += u[k]; }
            const float r = 1.0f / ssum;
            #pragma unroll
            for (int k = 0; k < KW; k++) u[k] *= r;

            if (it == NLAYERS - 1) {
                float* o = out + ((size_t)b * NQ + q) * KW;
                #pragma unroll
                for (int k = 0; k < KW; k++) o[k] = u[k];
            } else {
                #pragma unroll
                for (int k = 0; k < KW; k++) U_s[q * PADU + k] = u[k];
            }
        }
        if (it == NLAYERS - 1) break;
        __syncthreads();

        if (q < NQ) {
            float ng0 = 0.f, ng1 = 0.f, ng2 = 0.f, ng3 = 0.f, ng4 = 0.f;
            const float* Grow = &G[q * PADG];
            #pragma unroll 3
            for (int qp = 0; qp < NQ; qp += 5) {
                float  gv[5];
                float4 u4[5];
                float  u5[5];
                #pragma unroll
                for (int j = 0; j < 5; j++) {
                    gv[j] = Grow[qp + j];
                    u4[j] = *(const float4*)&U_s[(qp + j) * PADU];
                    u5[j] = U_s[(qp + j) * PADU + 4];
                }
                #pragma unroll
                for (int j = 0; j < 5; j++) {
                    ng0 += gv[j] * u4[j].x; ng1 += gv[j] * u4[j].y;
                    ng2 += gv[j] * u4[j].z; ng3 += gv[j] * u4[j].w;
                    ng4 += gv[j] * u5[j];
                }
            }
            gu[0] = ng0; gu[1] = ng1; gu[2] = ng2; gu[3] = ng3; gu[4] = ng4;
            GU_s[q * PADU + 0] = ng0; GU_s[q * PADU + 1] = ng1;
            GU_s[q * PADU + 2] = ng2; GU_s[q * PADU + 3] = ng3;
            GU_s[q * PADU + 4] = ng4;
        }
        __syncthreads();

        const int w = t >> 5, lane = t & 31;
        if (w < KW) {
            const int k = w;
            float usum = 0.f, ups = 0.f, ugu = 0.f;
            for (int qq = lane; qq < NQ; qq += 32) {
                const float uv = U_s[qq * PADU + k];
                usum += uv;
                ups  += uv * G[(NQ + k) * PADG + qq];
                ugu  += uv * GU_s[qq * PADU + k];
            }
            #pragma unroll
            for (int o = 16; o > 0; o >>= 1) {
                usum += __shfl_down_sync(0xffffffffu, usum, o);
                ups  += __shfl_down_sync(0xffffffffu, ups,  o);
                ugu  += __shfl_down_sync(0xffffffffu, ugu,  o);
            }
            if (lane == 0) {
                const float den = usum + cnt_s[k];
                const float iv  = 1.0f / den;
                const float nn  = ugu + 2.f * ups + ssq_s[k];
                invden_s[k] = iv;
                halfnn_s[k] = 0.5f * nn * iv * iv;
                gV_s[k]     = g * (logf(usum / (float)NQ + EPS) + 1.0f);
            }
        }
        __syncthreads();
    }
}

extern "C" void kernel_launch(void* const* d_in, const int* in_sizes, int n_in,
                              void* d_out, int out_size)
{
    const float* Zs = (const float*)d_in[0];
    const int*   Y  = (const int*)  d_in[1];
    const float* Zq = (const float*)d_in[2];
    const float* t1 = (const float*)d_in[3];
    const float* gm = (const float*)d_in[4];
    const float* t2 = (const float*)d_in[5];
    cudaFuncSetAttribute(fewshot_kernel,
                         cudaFuncAttributeMaxDynamicSharedMemorySize, SMEM_BYTES);
    fewshot_kernel<<<NTASK, NTHR, SMEM_BYTES>>>(Zs, Y, Zq, t1, gm, t2, (float*)d_out);
}